// round 7
// baseline (speedup 1.0000x reference)
#include <cuda_runtime.h>
#include <cuda_bf16.h>
#include <math.h>
#include <stdint.h>

// ---------------------------------------------------------------------------
// GatedDeltaNet, B=2,S=1024,H=2048,HV=32,HK=16,DK=DV=128,KW=4.
// Split-bf16 3-term mma.sync GEMMs (tcgen05 rejected by harness ptxas target).
// qkv+z merged into one N=12288 GEMM; conv+l2norm fused; shuffle recurrence.
// ---------------------------------------------------------------------------
#define BB   2
#define SS   1024
#define TT   (BB*SS)
#define HH   2048
#define HV   32
#define HK   16
#define DK   128
#define DV   128
#define KW   4
#define KEY_DIM  (HK*DK)             // 2048
#define VAL_DIM  (HV*DV)             // 4096
#define CONV_DIM (2*KEY_DIM+VAL_DIM) // 8192
#define NQZ  (CONV_DIM + VAL_DIM)    // 12288 merged qkv|z output width

// ------------------------- scratch (device globals) ------------------------
__device__ float g_pre [TT * NQZ];          // [x@Wqkv | x@Wz]
__device__ float g_v   [TT * VAL_DIM];      // conv+silu'd v
__device__ float g_qn  [TT * HV * DK];
__device__ float g_kn  [TT * HV * DK];
__device__ float g_g   [TT * HV];
__device__ float g_beta[TT * HV];
__device__ float g_core[TT * HV * DV];
// split-bf16 operands
__device__ __nv_bfloat16 g_xh[TT * HH],          g_xl[TT * HH];
__device__ __nv_bfloat16 g_WT_h[NQZ * HH],       g_WT_l[NQZ * HH];   // [Wqkv^T | Wz^T]
__device__ __nv_bfloat16 g_WoutT_h[HH * VAL_DIM], g_WoutT_l[HH * VAL_DIM];
__device__ __nv_bfloat16 g_nrm_h[TT * VAL_DIM],  g_nrm_l[TT * VAL_DIM];

// ---------------------------------------------------------------------------
// helpers
// ---------------------------------------------------------------------------
__device__ __forceinline__ void bsplit(float v, __nv_bfloat16& h, __nv_bfloat16& l) {
    h = __float2bfloat16(v);
    l = __float2bfloat16(v - __bfloat162float(h));
}

#define SWZ64(o) ((o) ^ (((o) >> 3) & 0x30))

#define CP16(dst, src)                                                         \
    asm volatile("cp.async.cg.shared.global [%0], [%1], 16;" ::                \
                 "r"(dst), "l"(src))

#define LDSM4(r0, r1, r2, r3, a)                                               \
    asm volatile("ldmatrix.sync.aligned.m8n8.x4.shared.b16 {%0,%1,%2,%3},[%4];"\
                 : "=r"(r0), "=r"(r1), "=r"(r2), "=r"(r3) : "r"(a))

#define MMA_BF16(d, a, b)                                                      \
    asm volatile("mma.sync.aligned.m16n8k16.row.col.f32.bf16.bf16.f32 "        \
                 "{%0,%1,%2,%3},{%4,%5,%6,%7},{%8,%9},{%0,%1,%2,%3};"          \
                 : "+f"((d)[0]), "+f"((d)[1]), "+f"((d)[2]), "+f"((d)[3])      \
                 : "r"((a)[0]), "r"((a)[1]), "r"((a)[2]), "r"((a)[3]),         \
                   "r"((b)[0]), "r"((b)[1]))

// ---------------------------------------------------------------------------
// Split-bf16 3-term GEMM: C[M,N] = (Ah+Al)[M,K] @ ((Bh+Bl)[N,K])^T
// CTA 128x128, 256 threads (8 warps of 64x32), BK=32, 3-stage cp.async,
// SW64-swizzled 64B rows, ONE __syncthreads per k-chunk.
// ---------------------------------------------------------------------------
#define BKE   32
#define TILEB 8192
#define OFF_AH 0
#define OFF_AL (1*TILEB)
#define OFF_BH (2*TILEB)
#define OFF_BL (3*TILEB)
#define STG    (4*TILEB)            // 32768 bytes per stage
#define NSTG   3
#define GEMM_SMEM (NSTG*STG)        // 98304

__device__ __forceinline__ void load_stage(
    const __nv_bfloat16* __restrict__ Ah, const __nv_bfloat16* __restrict__ Al,
    const __nv_bfloat16* __restrict__ Bh, const __nv_bfloat16* __restrict__ Bl,
    int bm, int bn, int K, int kc, uint32_t sbase, int tid)
{
#pragma unroll
    for (int i = 0; i < 2; i++) {
        int c    = tid + 256 * i;
        int row  = c >> 2;
        int k16  = c & 3;
        uint32_t off = SWZ64((uint32_t)(row * 64 + k16 * 16));
        size_t gofs = (size_t)kc * BKE + k16 * 8;
        CP16(sbase + OFF_AH + off, Ah + (size_t)(bm + row) * K + gofs);
        CP16(sbase + OFF_AL + off, Al + (size_t)(bm + row) * K + gofs);
        CP16(sbase + OFF_BH + off, Bh + (size_t)(bn + row) * K + gofs);
        CP16(sbase + OFF_BL + off, Bl + (size_t)(bn + row) * K + gofs);
    }
    asm volatile("cp.async.commit_group;" ::: "memory");
}

__global__ __launch_bounds__(256) void gemm_bf16_3t(
    const __nv_bfloat16* __restrict__ Ah, const __nv_bfloat16* __restrict__ Al,
    const __nv_bfloat16* __restrict__ Bh, const __nv_bfloat16* __restrict__ Bl,
    float* __restrict__ C, int M, int N, int K)
{
    extern __shared__ __align__(128) char smem[];
    const uint32_t sb = (uint32_t)__cvta_generic_to_shared(smem);
    const int tid  = threadIdx.x;
    const int lane = tid & 31;
    const int wid  = tid >> 5;
    const int wm   = (wid >> 2) * 64;
    const int wn   = (wid & 3) * 32;
    const int bm = blockIdx.y * 128;
    const int bn = blockIdx.x * 128;

    float acc[4][4][4];
#pragma unroll
    for (int mf = 0; mf < 4; mf++)
#pragma unroll
        for (int nf = 0; nf < 4; nf++)
#pragma unroll
            for (int i = 0; i < 4; i++) acc[mf][nf][i] = 0.f;

    const int NC = K / BKE;
    load_stage(Ah, Al, Bh, Bl, bm, bn, K, 0, sb + 0 * STG, tid);
    load_stage(Ah, Al, Bh, Bl, bm, bn, K, 1, sb + 1 * STG, tid);

    const int lrow = lane & 15;
    const int lkb  = (lane >> 4) * 16;

    int buf = 0, nxt = 2;
    for (int c = 0; c < NC; c++) {
        if (c + 1 < NC) asm volatile("cp.async.wait_group 1;" ::: "memory");
        else            asm volatile("cp.async.wait_group 0;" ::: "memory");
        __syncthreads();

        if (c + 2 < NC)
            load_stage(Ah, Al, Bh, Bl, bm, bn, K, c + 2, sb + nxt * STG, tid);

        const uint32_t base = sb + buf * STG;
#pragma unroll
        for (int ks = 0; ks < 2; ks++) {
            const int kb = ks * 32 + lkb;
            uint32_t ah[4][4], al[4][4], bh[4][2], bl[4][2];
#pragma unroll
            for (int mf = 0; mf < 4; mf++) {
                uint32_t off = SWZ64((uint32_t)((wm + mf * 16 + lrow) * 64 + kb));
                LDSM4(ah[mf][0], ah[mf][1], ah[mf][2], ah[mf][3], base + OFF_AH + off);
                LDSM4(al[mf][0], al[mf][1], al[mf][2], al[mf][3], base + OFF_AL + off);
            }
#pragma unroll
            for (int nf2 = 0; nf2 < 2; nf2++) {
                uint32_t off = SWZ64((uint32_t)((wn + nf2 * 16 + lrow) * 64 + kb));
                uint32_t t0, t1, t2, t3;
                LDSM4(t0, t1, t2, t3, base + OFF_BH + off);
                bh[nf2 * 2 + 0][0] = t0; bh[nf2 * 2 + 0][1] = t2;
                bh[nf2 * 2 + 1][0] = t1; bh[nf2 * 2 + 1][1] = t3;
                LDSM4(t0, t1, t2, t3, base + OFF_BL + off);
                bl[nf2 * 2 + 0][0] = t0; bl[nf2 * 2 + 0][1] = t2;
                bl[nf2 * 2 + 1][0] = t1; bl[nf2 * 2 + 1][1] = t3;
            }
#pragma unroll
            for (int mf = 0; mf < 4; mf++)
#pragma unroll
                for (int nf = 0; nf < 4; nf++) {
                    MMA_BF16(acc[mf][nf], ah[mf], bh[nf]);
                    MMA_BF16(acc[mf][nf], ah[mf], bl[nf]);
                    MMA_BF16(acc[mf][nf], al[mf], bh[nf]);
                }
        }

        buf = (buf + 1 == NSTG) ? 0 : buf + 1;
        nxt = (nxt + 1 == NSTG) ? 0 : nxt + 1;
    }

    const int g   = lane >> 2;
    const int tig = lane & 3;
#pragma unroll
    for (int mf = 0; mf < 4; mf++)
#pragma unroll
        for (int nf = 0; nf < 4; nf++) {
            int r  = bm + wm + mf * 16 + g;
            int cc = bn + wn + nf * 8 + tig * 2;
            *reinterpret_cast<float2*>(&C[(size_t)r * N + cc]) =
                make_float2(acc[mf][nf][0], acc[mf][nf][1]);
            *reinterpret_cast<float2*>(&C[(size_t)(r + 8) * N + cc]) =
                make_float2(acc[mf][nf][2], acc[mf][nf][3]);
        }
}

// ---------------------------------------------------------------------------
// split fp32 -> bf16 hi/lo (row-major, elementwise)
// ---------------------------------------------------------------------------
__global__ __launch_bounds__(256) void split_bf16(
    const float4* __restrict__ in, __nv_bfloat16* __restrict__ h,
    __nv_bfloat16* __restrict__ l, int n4)
{
    int i = blockIdx.x * 256 + threadIdx.x;
    if (i >= n4) return;
    float4 v = in[i];
    __nv_bfloat16 h0, l0, h1, l1, h2, l2, h3, l3;
    bsplit(v.x, h0, l0); bsplit(v.y, h1, l1);
    bsplit(v.z, h2, l2); bsplit(v.w, h3, l3);
    __nv_bfloat162* hp = (__nv_bfloat162*)(h + (size_t)i * 4);
    __nv_bfloat162* lp = (__nv_bfloat162*)(l + (size_t)i * 4);
    hp[0] = __nv_bfloat162(h0, h1); hp[1] = __nv_bfloat162(h2, h3);
    lp[0] = __nv_bfloat162(l0, l1); lp[1] = __nv_bfloat162(l2, l3);
}

// ---------------------------------------------------------------------------
// transpose + split: W[K][N] fp32 -> Th/Tl[N][K] bf16
// ---------------------------------------------------------------------------
__global__ __launch_bounds__(256) void split_bf16_T(
    const float* __restrict__ W, __nv_bfloat16* __restrict__ Th,
    __nv_bfloat16* __restrict__ Tl, int K, int N)
{
    __shared__ float tile[32][33];
    const int bx = blockIdx.x * 32;   // N
    const int by = blockIdx.y * 32;   // K
    const int tx = threadIdx.x & 31, ty = threadIdx.x >> 5;
#pragma unroll
    for (int i = 0; i < 32; i += 8)
        tile[ty + i][tx] = W[(size_t)(by + ty + i) * N + bx + tx];
    __syncthreads();
#pragma unroll
    for (int i = 0; i < 32; i += 8) {
        float v = tile[tx][ty + i];
        __nv_bfloat16 h, l;
        bsplit(v, h, l);
        size_t o = (size_t)(bx + ty + i) * K + by + tx;
        Th[o] = h; Tl[o] = l;
    }
}

// ---------------------------------------------------------------------------
// Fused causal conv + SiLU + l2norm for q/k. One CTA per (t, hk).
// Writes head-repeated qn/kn directly; q/k never round-trip through gmem raw.
// ---------------------------------------------------------------------------
__global__ __launch_bounds__(128) void conv_qk(
    const float* __restrict__ pre, const float* __restrict__ cw,
    const float* __restrict__ cb, float* __restrict__ qn,
    float* __restrict__ kn)
{
    const int blk = blockIdx.x;
    const int t = blk / HK, hk = blk % HK;
    const int dk = threadIdx.x;
    const int b = t / SS, s = t % SS;
    const int chq = hk * DK + dk;
    const int chk = KEY_DIM + hk * DK + dk;

    float aq = cb[chq], ak = cb[chk];
    const float4 wq = *reinterpret_cast<const float4*>(cw + chq * KW);
    const float4 wk = *reinterpret_cast<const float4*>(cw + chk * KW);
    const float* wqa = (const float*)&wq;
    const float* wka = (const float*)&wk;
#pragma unroll
    for (int j = 0; j < KW; j++) {
        int sp = s - (KW - 1) + j;
        if (sp >= 0) {
            size_t row = (size_t)(b * SS + sp) * NQZ;
            aq += pre[row + chq] * wqa[j];
            ak += pre[row + chk] * wka[j];
        }
    }
    float qv = aq / (1.f + expf(-aq));
    float kv = ak / (1.f + expf(-ak));

    __shared__ float s1[128], s2[128];
    s1[dk] = qv * qv;
    s2[dk] = kv * kv;
    __syncthreads();
#pragma unroll
    for (int off = 64; off > 0; off >>= 1) {
        if (dk < off) { s1[dk] += s1[dk + off]; s2[dk] += s2[dk + off]; }
        __syncthreads();
    }
    __shared__ float rq, rk;
    if (dk == 0) {
        rq = rsqrtf(s1[0] + 1e-6f);
        rk = rsqrtf(s2[0] + 1e-6f);
    }
    __syncthreads();

    float qo = qv * rq * 0.08838834764831845f;   // * DK^-0.5
    float ko = kv * rk;
    int h0 = hk * 2;
    size_t base0 = ((size_t)t * HV + h0) * DK + dk;
    size_t base1 = ((size_t)t * HV + h0 + 1) * DK + dk;
    qn[base0] = qo; qn[base1] = qo;
    kn[base0] = ko; kn[base1] = ko;
}

// ---------------------------------------------------------------------------
// Causal conv + SiLU for v channels only -> compact g_v[T][VAL_DIM]
// ---------------------------------------------------------------------------
__global__ __launch_bounds__(256) void conv_v(
    const float* __restrict__ pre, const float* __restrict__ cw,
    const float* __restrict__ cb, float* __restrict__ vout)
{
    int c  = blockIdx.x * 256 + threadIdx.x;   // 0..VAL_DIM-1
    int ch = 2 * KEY_DIM + c;                  // conv channel
    int t  = blockIdx.y;
    int b = t / SS, s = t % SS;
    float acc = cb[ch];
    const float4 w4 = *reinterpret_cast<const float4*>(cw + ch * KW);
    const float* wa = (const float*)&w4;
#pragma unroll
    for (int j = 0; j < KW; j++) {
        int sp = s - (KW - 1) + j;
        if (sp >= 0)
            acc += pre[(size_t)(b * SS + sp) * NQZ + ch] * wa[j];
    }
    vout[(size_t)t * VAL_DIM + c] = acc / (1.f + expf(-acc));
}

// ---------------------------------------------------------------------------
// beta / g projections
// ---------------------------------------------------------------------------
__global__ __launch_bounds__(256) void proj_gb(
    const float* __restrict__ x, const float* __restrict__ Wb,
    const float* __restrict__ Wa, const float* __restrict__ dt_bias,
    const float* __restrict__ A_log, float* __restrict__ gout,
    float* __restrict__ bout)
{
    int t = blockIdx.x;
    __shared__ float xs[HH];
    const float4* xr = reinterpret_cast<const float4*>(x + (size_t)t * HH);
    float4* xs4 = reinterpret_cast<float4*>(xs);
    for (int i = threadIdx.x; i < HH / 4; i += 256) xs4[i] = xr[i];
    __syncthreads();

    int out  = threadIdx.x >> 2;
    int part = threadIdx.x & 3;
    const float* W = (out < 32) ? Wb : Wa;
    int col = out & 31;

    float acc = 0.f;
    int k0 = part * (HH / 4);
#pragma unroll 8
    for (int k = k0; k < k0 + HH / 4; k++)
        acc += xs[k] * W[k * HV + col];

    acc += __shfl_xor_sync(0xffffffffu, acc, 1);
    acc += __shfl_xor_sync(0xffffffffu, acc, 2);

    if (part == 0) {
        if (out < 32) {
            bout[t * HV + col] = 1.f / (1.f + expf(-acc));
        } else {
            float v = acc + dt_bias[col];
            float sp = (v > 20.f) ? v : log1pf(expf(v));
            gout[t * HV + col] = -expf(A_log[col]) * sp;
        }
    }
}

// ---------------------------------------------------------------------------
// Gated delta-rule recurrence, 128 CTAs (2 per chain, dv-halved).
// Lane pairing: dv = warp*16 + (lane>>1), dkh = (lane&1)*64. Reductions via
// shfl_xor(1); ONE __syncthreads per step (k/q double-buffer handoff).
// ---------------------------------------------------------------------------
__global__ __launch_bounds__(128) void recurrence(
    const float* __restrict__ qn, const float* __restrict__ kn,
    const float* __restrict__ vbuf, const float* __restrict__ gg,
    const float* __restrict__ bb, float* __restrict__ core)
{
    const int cid   = blockIdx.x;          // 0..127
    const int chain = cid >> 1;            // b*HV + h
    const int dvh   = (cid & 1) * 64;
    const int b = chain / HV, h = chain % HV;
    const int tid  = threadIdx.x;
    const int lane = tid & 31;
    const int wrp  = tid >> 5;
    const int dvl  = wrp * 16 + (lane >> 1);   // 0..63
    const int dkh  = (lane & 1) * 64;          // 0 or 64
    const int dv   = dvh + dvl;

    float st[64];                           // S[dkh+i][dv]
#pragma unroll
    for (int i = 0; i < 64; i++) st[i] = 0.f;

    __shared__ float ks[2][DK], qs[2][DK];

    const int t0 = b * SS;
    ks[0][tid] = kn[((size_t)t0 * HV + h) * DK + tid];
    qs[0][tid] = qn[((size_t)t0 * HV + h) * DK + tid];
    float gv = gg[t0 * HV + h];
    float bv = bb[t0 * HV + h];
    float vv = vbuf[(size_t)t0 * VAL_DIM + h * DV + dv];
    __syncthreads();

    for (int s = 0; s < SS; s++) {
        const int cur = s & 1;
        const int t = b * SS + s;

        float knx = 0.f, qnx = 0.f, gnx = 0.f, bnx = 0.f, vnx = 0.f;
        if (s + 1 < SS) {
            int tn = t + 1;
            knx = kn[((size_t)tn * HV + h) * DK + tid];
            qnx = qn[((size_t)tn * HV + h) * DK + tid];
            gnx = gg[tn * HV + h];
            bnx = bb[tn * HV + h];
            vnx = vbuf[(size_t)tn * VAL_DIM + h * DV + dv];
        }

        const float dec = expf(gv);

        float m0 = 0.f, m1 = 0.f, m2 = 0.f, m3 = 0.f;
#pragma unroll
        for (int i = 0; i < 64; i += 4) {
            float4 kk = *reinterpret_cast<const float4*>(&ks[cur][dkh + i]);
            st[i + 0] *= dec; m0 += kk.x * st[i + 0];
            st[i + 1] *= dec; m1 += kk.y * st[i + 1];
            st[i + 2] *= dec; m2 += kk.z * st[i + 2];
            st[i + 3] *= dec; m3 += kk.w * st[i + 3];
        }
        float mloc = (m0 + m1) + (m2 + m3);
        const float mem = mloc + __shfl_xor_sync(0xffffffffu, mloc, 1);
        const float delta = (vv - mem) * bv;

        float o0 = 0.f, o1 = 0.f, o2 = 0.f, o3 = 0.f;
#pragma unroll
        for (int i = 0; i < 64; i += 4) {
            float4 kk = *reinterpret_cast<const float4*>(&ks[cur][dkh + i]);
            float4 qq = *reinterpret_cast<const float4*>(&qs[cur][dkh + i]);
            st[i + 0] += kk.x * delta; o0 += qq.x * st[i + 0];
            st[i + 1] += kk.y * delta; o1 += qq.y * st[i + 1];
            st[i + 2] += kk.z * delta; o2 += qq.z * st[i + 2];
            st[i + 3] += kk.w * delta; o3 += qq.w * st[i + 3];
        }
        float oloc = (o0 + o1) + (o2 + o3);
        const float out = oloc + __shfl_xor_sync(0xffffffffu, oloc, 1);
        if (dkh == 0)
            core[((size_t)t * HV + h) * DV + dv] = out;

        if (s + 1 < SS) {
            ks[cur ^ 1][tid] = knx;
            qs[cur ^ 1][tid] = qnx;
        }
        gv = gnx; bv = bnx; vv = vnx;
        __syncthreads();
    }
}

// ---------------------------------------------------------------------------
// gated RMSNorm -> bf16 hi/lo (z read from merged pre buffer)
// ---------------------------------------------------------------------------
__global__ __launch_bounds__(128) void gated_norm(
    const float* __restrict__ core, const float* __restrict__ pre,
    const float* __restrict__ nw, __nv_bfloat16* __restrict__ nh,
    __nv_bfloat16* __restrict__ nl)
{
    int bh = blockIdx.x;      // t*HV + h
    int t = bh / HV, h = bh % HV;
    int dv = threadIdx.x;
    size_t idx = (size_t)bh * DV + dv;

    float c  = core[idx];
    float zv = pre[(size_t)t * NQZ + CONV_DIM + h * DV + dv];
    float gz = c * (zv / (1.f + expf(-zv)));

    __shared__ float red[128];
    red[dv] = gz * gz;
    __syncthreads();
#pragma unroll
    for (int off = 64; off > 0; off >>= 1) {
        if (dv < off) red[dv] += red[dv + off];
        __syncthreads();
    }
    __shared__ float rs;
    if (dv == 0) rs = rsqrtf(red[0] * (1.f / DV) + 1e-6f);
    __syncthreads();

    __nv_bfloat16 h2, l2;
    bsplit(gz * rs * nw[dv], h2, l2);
    nh[idx] = h2; nl[idx] = l2;
}

// ---------------------------------------------------------------------------
// launch
// ---------------------------------------------------------------------------
extern "C" void kernel_launch(void* const* d_in, const int* in_sizes, int n_in,
                              void* d_out, int out_size)
{
    const float* x       = (const float*)d_in[0];
    const float* Wqkv    = (const float*)d_in[1];
    const float* Wz      = (const float*)d_in[2];
    const float* Wb      = (const float*)d_in[3];
    const float* Wa      = (const float*)d_in[4];
    const float* conv_w  = (const float*)d_in[5];
    const float* conv_b  = (const float*)d_in[6];
    const float* dt_bias = (const float*)d_in[7];
    const float* A_log   = (const float*)d_in[8];
    const float* norm_w  = (const float*)d_in[9];
    const float* Wout    = (const float*)d_in[10];
    float* out = (float*)d_out;

    float *pre, *vbuf, *qn, *kn, *gbuf, *bbuf, *core;
    __nv_bfloat16 *xh, *xl, *WT_h, *WT_l, *WoT_h, *WoT_l, *nh, *nl;
    cudaGetSymbolAddress((void**)&pre,   g_pre);
    cudaGetSymbolAddress((void**)&vbuf,  g_v);
    cudaGetSymbolAddress((void**)&qn,    g_qn);
    cudaGetSymbolAddress((void**)&kn,    g_kn);
    cudaGetSymbolAddress((void**)&gbuf,  g_g);
    cudaGetSymbolAddress((void**)&bbuf,  g_beta);
    cudaGetSymbolAddress((void**)&core,  g_core);
    cudaGetSymbolAddress((void**)&xh,    g_xh);
    cudaGetSymbolAddress((void**)&xl,    g_xl);
    cudaGetSymbolAddress((void**)&WT_h,  g_WT_h);
    cudaGetSymbolAddress((void**)&WT_l,  g_WT_l);
    cudaGetSymbolAddress((void**)&WoT_h, g_WoutT_h);
    cudaGetSymbolAddress((void**)&WoT_l, g_WoutT_l);
    cudaGetSymbolAddress((void**)&nh,    g_nrm_h);
    cudaGetSymbolAddress((void**)&nl,    g_nrm_l);

    cudaFuncSetAttribute(gemm_bf16_3t,
        cudaFuncAttributeMaxDynamicSharedMemorySize, GEMM_SMEM);

    // 0) operand prep
    split_bf16<<<(TT * HH / 4 + 255) / 256, 256>>>(
        (const float4*)x, xh, xl, TT * HH / 4);
    split_bf16_T<<<dim3(CONV_DIM / 32, HH / 32), 256>>>(
        Wqkv, WT_h, WT_l, HH, CONV_DIM);
    split_bf16_T<<<dim3(VAL_DIM / 32, HH / 32), 256>>>(
        Wz, WT_h + (size_t)CONV_DIM * HH, WT_l + (size_t)CONV_DIM * HH,
        HH, VAL_DIM);
    split_bf16_T<<<dim3(HH / 32, VAL_DIM / 32), 256>>>(
        Wout, WoT_h, WoT_l, VAL_DIM, HH);
    proj_gb<<<TT, 256>>>(x, Wb, Wa, dt_bias, A_log, gbuf, bbuf);

    // 1) merged qkv+z projection (one N=12288 GEMM)
    gemm_bf16_3t<<<dim3(NQZ / 128, TT / 128), 256, GEMM_SMEM>>>(
        xh, xl, WT_h, WT_l, pre, TT, NQZ, HH);

    // 2) fused conv+silu(+l2norm for q/k)
    conv_qk<<<TT * HK, 128>>>(pre, conv_w, conv_b, qn, kn);
    conv_v<<<dim3(VAL_DIM / 256, TT), 256>>>(pre, conv_w, conv_b, vbuf);

    // 3) recurrence
    recurrence<<<BB * HV * 2, 128>>>(qn, kn, vbuf, gbuf, bbuf, core);

    // 4) gated RMSNorm -> bf16 hi/lo
    gated_norm<<<TT * HV, 128>>>(core, pre, norm_w, nh, nl);

    // 5) output projection
    gemm_bf16_3t<<<dim3(HH / 128, TT / 128), 256, GEMM_SMEM>>>(
        nh, nl, WoT_h, WoT_l, out, TT, HH, VAL_DIM);
}

// round 8
// speedup vs baseline: 1.1236x; 1.1236x over previous
#include <cuda_runtime.h>
#include <cuda_bf16.h>
#include <math.h>
#include <stdint.h>

// ---------------------------------------------------------------------------
// GatedDeltaNet, B=2,S=1024,H=2048,HV=32,HK=16,DK=DV=128,KW=4.
// Round-6 proven kernels + two-stream overlap: z-GEMM runs concurrently with
// conv/qk_prep/recurrence; weight splits + proj_gb overlap the qkv GEMM.
// ---------------------------------------------------------------------------
#define BB   2
#define SS   1024
#define TT   (BB*SS)
#define HH   2048
#define HV   32
#define HK   16
#define DK   128
#define DV   128
#define KW   4
#define KEY_DIM  (HK*DK)             // 2048
#define VAL_DIM  (HV*DV)             // 4096
#define CONV_DIM (2*KEY_DIM+VAL_DIM) // 8192

// ------------------------- scratch (device globals) ------------------------
__device__ float g_qkv_pre[TT * CONV_DIM];
__device__ float g_mixed  [TT * CONV_DIM];
__device__ float g_z      [TT * VAL_DIM];
__device__ float g_qn     [TT * HV * DK];
__device__ float g_kn     [TT * HV * DK];
__device__ float g_g      [TT * HV];
__device__ float g_beta   [TT * HV];
__device__ float g_core   [TT * HV * DV];
// split-bf16 operands
__device__ __nv_bfloat16 g_xh[TT * HH],            g_xl[TT * HH];
__device__ __nv_bfloat16 g_WqkvT_h[CONV_DIM * HH], g_WqkvT_l[CONV_DIM * HH];
__device__ __nv_bfloat16 g_WzT_h[VAL_DIM * HH],    g_WzT_l[VAL_DIM * HH];
__device__ __nv_bfloat16 g_WoutT_h[HH * VAL_DIM],  g_WoutT_l[HH * VAL_DIM];
__device__ __nv_bfloat16 g_nrm_h[TT * VAL_DIM],    g_nrm_l[TT * VAL_DIM];

// ---------------------------------------------------------------------------
// helpers
// ---------------------------------------------------------------------------
__device__ __forceinline__ void bsplit(float v, __nv_bfloat16& h, __nv_bfloat16& l) {
    h = __float2bfloat16(v);
    l = __float2bfloat16(v - __bfloat162float(h));
}

#define SWZ64(o) ((o) ^ (((o) >> 3) & 0x30))

#define CP16(dst, src)                                                         \
    asm volatile("cp.async.cg.shared.global [%0], [%1], 16;" ::                \
                 "r"(dst), "l"(src))

#define LDSM4(r0, r1, r2, r3, a)                                               \
    asm volatile("ldmatrix.sync.aligned.m8n8.x4.shared.b16 {%0,%1,%2,%3},[%4];"\
                 : "=r"(r0), "=r"(r1), "=r"(r2), "=r"(r3) : "r"(a))

#define MMA_BF16(d, a, b)                                                      \
    asm volatile("mma.sync.aligned.m16n8k16.row.col.f32.bf16.bf16.f32 "        \
                 "{%0,%1,%2,%3},{%4,%5,%6,%7},{%8,%9},{%0,%1,%2,%3};"          \
                 : "+f"((d)[0]), "+f"((d)[1]), "+f"((d)[2]), "+f"((d)[3])      \
                 : "r"((a)[0]), "r"((a)[1]), "r"((a)[2]), "r"((a)[3]),         \
                   "r"((b)[0]), "r"((b)[1]))

// ---------------------------------------------------------------------------
// Split-bf16 3-term GEMM: C[M,N] = (Ah+Al)[M,K] @ ((Bh+Bl)[N,K])^T
// CTA 128x128, 256 threads (8 warps of 64x32), BK=32, 3-stage cp.async,
// SW64-swizzled 64B rows, ONE __syncthreads per k-chunk.
// ---------------------------------------------------------------------------
#define BKE   32
#define TILEB 8192
#define OFF_AH 0
#define OFF_AL (1*TILEB)
#define OFF_BH (2*TILEB)
#define OFF_BL (3*TILEB)
#define STG    (4*TILEB)            // 32768 bytes per stage
#define NSTG   3
#define GEMM_SMEM (NSTG*STG)        // 98304

__device__ __forceinline__ void load_stage(
    const __nv_bfloat16* __restrict__ Ah, const __nv_bfloat16* __restrict__ Al,
    const __nv_bfloat16* __restrict__ Bh, const __nv_bfloat16* __restrict__ Bl,
    int bm, int bn, int K, int kc, uint32_t sbase, int tid)
{
#pragma unroll
    for (int i = 0; i < 2; i++) {
        int c    = tid + 256 * i;
        int row  = c >> 2;
        int k16  = c & 3;
        uint32_t off = SWZ64((uint32_t)(row * 64 + k16 * 16));
        size_t gofs = (size_t)kc * BKE + k16 * 8;
        CP16(sbase + OFF_AH + off, Ah + (size_t)(bm + row) * K + gofs);
        CP16(sbase + OFF_AL + off, Al + (size_t)(bm + row) * K + gofs);
        CP16(sbase + OFF_BH + off, Bh + (size_t)(bn + row) * K + gofs);
        CP16(sbase + OFF_BL + off, Bl + (size_t)(bn + row) * K + gofs);
    }
    asm volatile("cp.async.commit_group;" ::: "memory");
}

__global__ __launch_bounds__(256) void gemm_bf16_3t(
    const __nv_bfloat16* __restrict__ Ah, const __nv_bfloat16* __restrict__ Al,
    const __nv_bfloat16* __restrict__ Bh, const __nv_bfloat16* __restrict__ Bl,
    float* __restrict__ C, int M, int N, int K)
{
    extern __shared__ __align__(128) char smem[];
    const uint32_t sb = (uint32_t)__cvta_generic_to_shared(smem);
    const int tid  = threadIdx.x;
    const int lane = tid & 31;
    const int wid  = tid >> 5;
    const int wm   = (wid >> 2) * 64;
    const int wn   = (wid & 3) * 32;
    const int bm = blockIdx.y * 128;
    const int bn = blockIdx.x * 128;

    float acc[4][4][4];
#pragma unroll
    for (int mf = 0; mf < 4; mf++)
#pragma unroll
        for (int nf = 0; nf < 4; nf++)
#pragma unroll
            for (int i = 0; i < 4; i++) acc[mf][nf][i] = 0.f;

    const int NC = K / BKE;
    load_stage(Ah, Al, Bh, Bl, bm, bn, K, 0, sb + 0 * STG, tid);
    load_stage(Ah, Al, Bh, Bl, bm, bn, K, 1, sb + 1 * STG, tid);

    const int lrow = lane & 15;
    const int lkb  = (lane >> 4) * 16;

    int buf = 0, nxt = 2;
    for (int c = 0; c < NC; c++) {
        if (c + 1 < NC) asm volatile("cp.async.wait_group 1;" ::: "memory");
        else            asm volatile("cp.async.wait_group 0;" ::: "memory");
        __syncthreads();

        if (c + 2 < NC)
            load_stage(Ah, Al, Bh, Bl, bm, bn, K, c + 2, sb + nxt * STG, tid);

        const uint32_t base = sb + buf * STG;
#pragma unroll
        for (int ks = 0; ks < 2; ks++) {
            const int kb = ks * 32 + lkb;
            uint32_t ah[4][4], al[4][4], bh[4][2], bl[4][2];
#pragma unroll
            for (int mf = 0; mf < 4; mf++) {
                uint32_t off = SWZ64((uint32_t)((wm + mf * 16 + lrow) * 64 + kb));
                LDSM4(ah[mf][0], ah[mf][1], ah[mf][2], ah[mf][3], base + OFF_AH + off);
                LDSM4(al[mf][0], al[mf][1], al[mf][2], al[mf][3], base + OFF_AL + off);
            }
#pragma unroll
            for (int nf2 = 0; nf2 < 2; nf2++) {
                uint32_t off = SWZ64((uint32_t)((wn + nf2 * 16 + lrow) * 64 + kb));
                uint32_t t0, t1, t2, t3;
                LDSM4(t0, t1, t2, t3, base + OFF_BH + off);
                bh[nf2 * 2 + 0][0] = t0; bh[nf2 * 2 + 0][1] = t2;
                bh[nf2 * 2 + 1][0] = t1; bh[nf2 * 2 + 1][1] = t3;
                LDSM4(t0, t1, t2, t3, base + OFF_BL + off);
                bl[nf2 * 2 + 0][0] = t0; bl[nf2 * 2 + 0][1] = t2;
                bl[nf2 * 2 + 1][0] = t1; bl[nf2 * 2 + 1][1] = t3;
            }
#pragma unroll
            for (int mf = 0; mf < 4; mf++)
#pragma unroll
                for (int nf = 0; nf < 4; nf++) {
                    MMA_BF16(acc[mf][nf], ah[mf], bh[nf]);
                    MMA_BF16(acc[mf][nf], ah[mf], bl[nf]);
                    MMA_BF16(acc[mf][nf], al[mf], bh[nf]);
                }
        }

        buf = (buf + 1 == NSTG) ? 0 : buf + 1;
        nxt = (nxt + 1 == NSTG) ? 0 : nxt + 1;
    }

    const int g   = lane >> 2;
    const int tig = lane & 3;
#pragma unroll
    for (int mf = 0; mf < 4; mf++)
#pragma unroll
        for (int nf = 0; nf < 4; nf++) {
            int r  = bm + wm + mf * 16 + g;
            int cc = bn + wn + nf * 8 + tig * 2;
            *reinterpret_cast<float2*>(&C[(size_t)r * N + cc]) =
                make_float2(acc[mf][nf][0], acc[mf][nf][1]);
            *reinterpret_cast<float2*>(&C[(size_t)(r + 8) * N + cc]) =
                make_float2(acc[mf][nf][2], acc[mf][nf][3]);
        }
}

// ---------------------------------------------------------------------------
// split fp32 -> bf16 hi/lo (row-major, elementwise)
// ---------------------------------------------------------------------------
__global__ __launch_bounds__(256) void split_bf16(
    const float4* __restrict__ in, __nv_bfloat16* __restrict__ h,
    __nv_bfloat16* __restrict__ l, int n4)
{
    int i = blockIdx.x * 256 + threadIdx.x;
    if (i >= n4) return;
    float4 v = in[i];
    __nv_bfloat16 h0, l0, h1, l1, h2, l2, h3, l3;
    bsplit(v.x, h0, l0); bsplit(v.y, h1, l1);
    bsplit(v.z, h2, l2); bsplit(v.w, h3, l3);
    __nv_bfloat162* hp = (__nv_bfloat162*)(h + (size_t)i * 4);
    __nv_bfloat162* lp = (__nv_bfloat162*)(l + (size_t)i * 4);
    hp[0] = __nv_bfloat162(h0, h1); hp[1] = __nv_bfloat162(h2, h3);
    lp[0] = __nv_bfloat162(l0, l1); lp[1] = __nv_bfloat162(l2, l3);
}

// ---------------------------------------------------------------------------
// transpose + split: W[K][N] fp32 -> Th/Tl[N][K] bf16
// ---------------------------------------------------------------------------
__global__ __launch_bounds__(256) void split_bf16_T(
    const float* __restrict__ W, __nv_bfloat16* __restrict__ Th,
    __nv_bfloat16* __restrict__ Tl, int K, int N)
{
    __shared__ float tile[32][33];
    const int bx = blockIdx.x * 32;   // N
    const int by = blockIdx.y * 32;   // K
    const int tx = threadIdx.x & 31, ty = threadIdx.x >> 5;
#pragma unroll
    for (int i = 0; i < 32; i += 8)
        tile[ty + i][tx] = W[(size_t)(by + ty + i) * N + bx + tx];
    __syncthreads();
#pragma unroll
    for (int i = 0; i < 32; i += 8) {
        float v = tile[tx][ty + i];
        __nv_bfloat16 h, l;
        bsplit(v, h, l);
        size_t o = (size_t)(bx + ty + i) * K + by + tx;
        Th[o] = h; Tl[o] = l;
    }
}

// ---------------------------------------------------------------------------
// Causal depthwise conv (KW=4) + SiLU
// ---------------------------------------------------------------------------
__global__ __launch_bounds__(256) void conv_silu(
    const float* __restrict__ pre, const float* __restrict__ cw,
    const float* __restrict__ cb, float* __restrict__ out)
{
    int c = blockIdx.x * 256 + threadIdx.x;
    int t = blockIdx.y;
    int b = t / SS, s = t % SS;
    float acc = cb[c];
#pragma unroll
    for (int j = 0; j < KW; j++) {
        int sp = s - (KW - 1) + j;
        if (sp >= 0)
            acc += pre[(size_t)(b * SS + sp) * CONV_DIM + c] * cw[c * KW + j];
    }
    out[(size_t)t * CONV_DIM + c] = acc / (1.f + expf(-acc));
}

// ---------------------------------------------------------------------------
// beta / g projections
// ---------------------------------------------------------------------------
__global__ __launch_bounds__(256) void proj_gb(
    const float* __restrict__ x, const float* __restrict__ Wb,
    const float* __restrict__ Wa, const float* __restrict__ dt_bias,
    const float* __restrict__ A_log, float* __restrict__ gout,
    float* __restrict__ bout)
{
    int t = blockIdx.x;
    __shared__ float xs[HH];
    const float4* xr = reinterpret_cast<const float4*>(x + (size_t)t * HH);
    float4* xs4 = reinterpret_cast<float4*>(xs);
    for (int i = threadIdx.x; i < HH / 4; i += 256) xs4[i] = xr[i];
    __syncthreads();

    int out  = threadIdx.x >> 2;
    int part = threadIdx.x & 3;
    const float* W = (out < 32) ? Wb : Wa;
    int col = out & 31;

    float acc = 0.f;
    int k0 = part * (HH / 4);
#pragma unroll 8
    for (int k = k0; k < k0 + HH / 4; k++)
        acc += xs[k] * W[k * HV + col];

    acc += __shfl_xor_sync(0xffffffffu, acc, 1);
    acc += __shfl_xor_sync(0xffffffffu, acc, 2);

    if (part == 0) {
        if (out < 32) {
            bout[t * HV + col] = 1.f / (1.f + expf(-acc));
        } else {
            float v = acc + dt_bias[col];
            float sp = (v > 20.f) ? v : log1pf(expf(v));
            gout[t * HV + col] = -expf(A_log[col]) * sp;
        }
    }
}

// ---------------------------------------------------------------------------
// q/k l2-normalization + head-repeat
// ---------------------------------------------------------------------------
__global__ __launch_bounds__(128) void qk_prep(
    const float* __restrict__ mixed, float* __restrict__ qn,
    float* __restrict__ kn)
{
    int blk = blockIdx.x;
    int t = blk / HK, hk = blk % HK;
    int dk = threadIdx.x;

    float qv = mixed[(size_t)t * CONV_DIM + hk * DK + dk];
    float kv = mixed[(size_t)t * CONV_DIM + KEY_DIM + hk * DK + dk];

    __shared__ float s1[128], s2[128];
    s1[dk] = qv * qv;
    s2[dk] = kv * kv;
    __syncthreads();
#pragma unroll
    for (int off = 64; off > 0; off >>= 1) {
        if (dk < off) { s1[dk] += s1[dk + off]; s2[dk] += s2[dk + off]; }
        __syncthreads();
    }
    __shared__ float rq, rk;
    if (dk == 0) {
        rq = rsqrtf(s1[0] + 1e-6f);
        rk = rsqrtf(s2[0] + 1e-6f);
    }
    __syncthreads();

    float qo = qv * rq * 0.08838834764831845f;
    float ko = kv * rk;
    int h0 = hk * 2;
    size_t base0 = ((size_t)t * HV + h0) * DK + dk;
    size_t base1 = ((size_t)t * HV + h0 + 1) * DK + dk;
    qn[base0] = qo; qn[base1] = qo;
    kn[base0] = ko; kn[base1] = ko;
}

// ---------------------------------------------------------------------------
// Gated delta-rule recurrence, 128 CTAs (2 per chain, dv-halved), smem-reduce.
// ---------------------------------------------------------------------------
__global__ __launch_bounds__(128) void recurrence(
    const float* __restrict__ qn, const float* __restrict__ kn,
    const float* __restrict__ mixed, const float* __restrict__ gg,
    const float* __restrict__ bb, float* __restrict__ core)
{
    const int cid   = blockIdx.x;          // 0..127
    const int chain = cid >> 1;            // b*HV + h
    const int dvh   = (cid & 1) * 64;
    const int b = chain / HV, h = chain % HV;
    const int tid = threadIdx.x;
    const int dvl = tid & 63;
    const int dkh = (tid >> 6) * 64;
    const int dv  = dvh + dvl;

    float st[64];
#pragma unroll
    for (int i = 0; i < 64; i++) st[i] = 0.f;

    __shared__ float ks[2][DK], qs[2][DK], red1[128], red2[128];

    const int t0 = b * SS;
    ks[0][tid] = kn[((size_t)t0 * HV + h) * DK + tid];
    qs[0][tid] = qn[((size_t)t0 * HV + h) * DK + tid];
    float gv = gg[t0 * HV + h];
    float bv = bb[t0 * HV + h];
    float vv = mixed[(size_t)t0 * CONV_DIM + 2 * KEY_DIM + h * DV + dv];
    __syncthreads();

    for (int s = 0; s < SS; s++) {
        const int cur = s & 1;
        const int t = b * SS + s;

        float knx = 0.f, qnx = 0.f, gnx = 0.f, bnx = 0.f, vnx = 0.f;
        if (s + 1 < SS) {
            int tn = t + 1;
            knx = kn[((size_t)tn * HV + h) * DK + tid];
            qnx = qn[((size_t)tn * HV + h) * DK + tid];
            gnx = gg[tn * HV + h];
            bnx = bb[tn * HV + h];
            vnx = mixed[(size_t)tn * CONV_DIM + 2 * KEY_DIM + h * DV + dv];
        }

        const float dec = expf(gv);

        float m0 = 0.f, m1 = 0.f, m2 = 0.f, m3 = 0.f;
#pragma unroll
        for (int i = 0; i < 64; i += 4) {
            float4 kk = *reinterpret_cast<const float4*>(&ks[cur][dkh + i]);
            st[i + 0] *= dec; m0 += kk.x * st[i + 0];
            st[i + 1] *= dec; m1 += kk.y * st[i + 1];
            st[i + 2] *= dec; m2 += kk.z * st[i + 2];
            st[i + 3] *= dec; m3 += kk.w * st[i + 3];
        }
        red1[tid] = (m0 + m1) + (m2 + m3);
        __syncthreads();
        const float mem = red1[tid] + red1[tid ^ 64];
        const float delta = (vv - mem) * bv;

        float o0 = 0.f, o1 = 0.f, o2 = 0.f, o3 = 0.f;
#pragma unroll
        for (int i = 0; i < 64; i += 4) {
            float4 kk = *reinterpret_cast<const float4*>(&ks[cur][dkh + i]);
            float4 qq = *reinterpret_cast<const float4*>(&qs[cur][dkh + i]);
            st[i + 0] += kk.x * delta; o0 += qq.x * st[i + 0];
            st[i + 1] += kk.y * delta; o1 += qq.y * st[i + 1];
            st[i + 2] += kk.z * delta; o2 += qq.z * st[i + 2];
            st[i + 3] += kk.w * delta; o3 += qq.w * st[i + 3];
        }
        red2[tid] = (o0 + o1) + (o2 + o3);

        if (s + 1 < SS) {
            ks[cur ^ 1][tid] = knx;
            qs[cur ^ 1][tid] = qnx;
        }
        __syncthreads();
        if (dkh == 0)
            core[((size_t)t * HV + h) * DV + dv] = red2[tid] + red2[tid ^ 64];

        gv = gnx; bv = bnx; vv = vnx;
    }
}

// ---------------------------------------------------------------------------
// gated RMSNorm -> bf16 hi/lo (feeds out-projection)
// ---------------------------------------------------------------------------
__global__ __launch_bounds__(128) void gated_norm(
    const float* __restrict__ core, const float* __restrict__ z,
    const float* __restrict__ nw, __nv_bfloat16* __restrict__ nh,
    __nv_bfloat16* __restrict__ nl)
{
    int bh = blockIdx.x;
    int dv = threadIdx.x;
    size_t idx = (size_t)bh * DV + dv;

    float c  = core[idx];
    float zv = z[idx];
    float gz = c * (zv / (1.f + expf(-zv)));

    __shared__ float red[128];
    red[dv] = gz * gz;
    __syncthreads();
#pragma unroll
    for (int off = 64; off > 0; off >>= 1) {
        if (dv < off) red[dv] += red[dv + off];
        __syncthreads();
    }
    __shared__ float rs;
    if (dv == 0) rs = rsqrtf(red[0] * (1.f / DV) + 1e-6f);
    __syncthreads();

    __nv_bfloat16 h, l;
    bsplit(gz * rs * nw[dv], h, l);
    nh[idx] = h; nl[idx] = l;
}

// ---------------------------------------------------------------------------
// launch — two-stream overlap via event fork/join (graph-capturable)
// ---------------------------------------------------------------------------
extern "C" void kernel_launch(void* const* d_in, const int* in_sizes, int n_in,
                              void* d_out, int out_size)
{
    const float* x       = (const float*)d_in[0];
    const float* Wqkv    = (const float*)d_in[1];
    const float* Wz      = (const float*)d_in[2];
    const float* Wb      = (const float*)d_in[3];
    const float* Wa      = (const float*)d_in[4];
    const float* conv_w  = (const float*)d_in[5];
    const float* conv_b  = (const float*)d_in[6];
    const float* dt_bias = (const float*)d_in[7];
    const float* A_log   = (const float*)d_in[8];
    const float* norm_w  = (const float*)d_in[9];
    const float* Wout    = (const float*)d_in[10];
    float* out = (float*)d_out;

    float *qkv_pre, *mixed, *z, *qn, *kn, *gbuf, *bbuf, *core;
    __nv_bfloat16 *xh, *xl, *WqT_h, *WqT_l, *WzT_h, *WzT_l, *WoT_h, *WoT_l, *nh, *nl;
    cudaGetSymbolAddress((void**)&qkv_pre, g_qkv_pre);
    cudaGetSymbolAddress((void**)&mixed,   g_mixed);
    cudaGetSymbolAddress((void**)&z,       g_z);
    cudaGetSymbolAddress((void**)&qn,      g_qn);
    cudaGetSymbolAddress((void**)&kn,      g_kn);
    cudaGetSymbolAddress((void**)&gbuf,    g_g);
    cudaGetSymbolAddress((void**)&bbuf,    g_beta);
    cudaGetSymbolAddress((void**)&core,    g_core);
    cudaGetSymbolAddress((void**)&xh,      g_xh);
    cudaGetSymbolAddress((void**)&xl,      g_xl);
    cudaGetSymbolAddress((void**)&WqT_h,   g_WqkvT_h);
    cudaGetSymbolAddress((void**)&WqT_l,   g_WqkvT_l);
    cudaGetSymbolAddress((void**)&WzT_h,   g_WzT_h);
    cudaGetSymbolAddress((void**)&WzT_l,   g_WzT_l);
    cudaGetSymbolAddress((void**)&WoT_h,   g_WoutT_h);
    cudaGetSymbolAddress((void**)&WoT_l,   g_WoutT_l);
    cudaGetSymbolAddress((void**)&nh,      g_nrm_h);
    cudaGetSymbolAddress((void**)&nl,      g_nrm_l);

    static cudaStream_t s1 = nullptr;
    static cudaEvent_t ev_root, ev_prep, ev_qkv, ev_z;
    if (!s1) {
        cudaStreamCreateWithFlags(&s1, cudaStreamNonBlocking);
        cudaEventCreateWithFlags(&ev_root, cudaEventDisableTiming);
        cudaEventCreateWithFlags(&ev_prep, cudaEventDisableTiming);
        cudaEventCreateWithFlags(&ev_qkv,  cudaEventDisableTiming);
        cudaEventCreateWithFlags(&ev_z,    cudaEventDisableTiming);
        cudaFuncSetAttribute(gemm_bf16_3t,
            cudaFuncAttributeMaxDynamicSharedMemorySize, GEMM_SMEM);
    }

    // fork side stream off the main (default) stream
    cudaEventRecord(ev_root, 0);
    cudaStreamWaitEvent(s1, ev_root, 0);

    // main stream: x split + Wqkv split -> qkv GEMM
    split_bf16<<<(TT * HH / 4 + 255) / 256, 256>>>(
        (const float4*)x, xh, xl, TT * HH / 4);
    split_bf16_T<<<dim3(CONV_DIM / 32, HH / 32), 256>>>(
        Wqkv, WqT_h, WqT_l, HH, CONV_DIM);

    // side stream: Wz/Wout splits + proj_gb (overlap with qkv GEMM)
    split_bf16_T<<<dim3(VAL_DIM / 32, HH / 32), 256, 0, s1>>>(
        Wz, WzT_h, WzT_l, HH, VAL_DIM);
    split_bf16_T<<<dim3(HH / 32, VAL_DIM / 32), 256, 0, s1>>>(
        Wout, WoT_h, WoT_l, VAL_DIM, HH);
    proj_gb<<<TT, 256, 0, s1>>>(x, Wb, Wa, dt_bias, A_log, gbuf, bbuf);
    cudaEventRecord(ev_prep, s1);

    // main: qkv GEMM
    gemm_bf16_3t<<<dim3(CONV_DIM / 128, TT / 128), 256, GEMM_SMEM>>>(
        xh, xl, WqT_h, WqT_l, qkv_pre, TT, CONV_DIM, HH);
    cudaEventRecord(ev_qkv, 0);

    // side: z GEMM starts after qkv GEMM -> overlaps conv/qk_prep/recurrence
    cudaStreamWaitEvent(s1, ev_qkv, 0);
    gemm_bf16_3t<<<dim3(VAL_DIM / 128, TT / 128), 256, GEMM_SMEM, s1>>>(
        xh, xl, WzT_h, WzT_l, z, TT, VAL_DIM, HH);
    cudaEventRecord(ev_z, s1);

    // main: conv + qk prep + recurrence (recurrence needs proj_gb)
    conv_silu<<<dim3(CONV_DIM / 256, TT), 256>>>(qkv_pre, conv_w, conv_b, mixed);
    qk_prep<<<TT * HK, 128>>>(mixed, qn, kn);
    cudaStreamWaitEvent(0, ev_prep, 0);
    recurrence<<<BB * HV * 2, 128>>>(qn, kn, mixed, gbuf, bbuf, core);

    // join: gated_norm needs z (side stream) + core (main)
    cudaStreamWaitEvent(0, ev_z, 0);
    gated_norm<<<TT * HV, 128>>>(core, z, norm_w, nh, nl);

    // output projection (Wout split ordered via ev_z join on s1 program order)
    gemm_bf16_3t<<<dim3(HH / 128, TT / 128), 256, GEMM_SMEM>>>(
        nh, nl, WoT_h, WoT_l, out, TT, HH, VAL_DIM);
}

// round 9
// speedup vs baseline: 1.1634x; 1.0354x over previous
#include <cuda_runtime.h>
#include <cuda_bf16.h>
#include <math.h>
#include <stdint.h>

// ---------------------------------------------------------------------------
// GatedDeltaNet, B=2,S=1024,H=2048,HV=32,HK=16,DK=DV=128,KW=4.
// Round-8 proven kernels + deeper pipelining: recurrence chunked in time
// (exact fp32 state carry), z GEMM chunked by token rows, 3-stream overlap
// so gated_norm + out-GEMM slices run concurrently with rec chunk 2.
// ---------------------------------------------------------------------------
#define BB   2
#define SS   1024
#define TT   (BB*SS)
#define HH   2048
#define HV   32
#define HK   16
#define DK   128
#define DV   128
#define KW   4
#define KEY_DIM  (HK*DK)             // 2048
#define VAL_DIM  (HV*DV)             // 4096
#define CONV_DIM (2*KEY_DIM+VAL_DIM) // 8192
#define SHALF (SS/2)                 // 512

// ------------------------- scratch (device globals) ------------------------
__device__ float g_qkv_pre[TT * CONV_DIM];
__device__ float g_mixed  [TT * CONV_DIM];
__device__ float g_z      [TT * VAL_DIM];
__device__ float g_qn     [TT * HV * DK];
__device__ float g_kn     [TT * HV * DK];
__device__ float g_g      [TT * HV];
__device__ float g_beta   [TT * HV];
__device__ float g_core   [TT * HV * DV];
__device__ float g_state  [BB * HV * DK * DV];   // rec chunk state carry (4MB)
// split-bf16 operands
__device__ __nv_bfloat16 g_xh[TT * HH],            g_xl[TT * HH];
__device__ __nv_bfloat16 g_WqkvT_h[CONV_DIM * HH], g_WqkvT_l[CONV_DIM * HH];
__device__ __nv_bfloat16 g_WzT_h[VAL_DIM * HH],    g_WzT_l[VAL_DIM * HH];
__device__ __nv_bfloat16 g_WoutT_h[HH * VAL_DIM],  g_WoutT_l[HH * VAL_DIM];
__device__ __nv_bfloat16 g_nrm_h[TT * VAL_DIM],    g_nrm_l[TT * VAL_DIM];

// ---------------------------------------------------------------------------
// helpers
// ---------------------------------------------------------------------------
__device__ __forceinline__ void bsplit(float v, __nv_bfloat16& h, __nv_bfloat16& l) {
    h = __float2bfloat16(v);
    l = __float2bfloat16(v - __bfloat162float(h));
}

#define SWZ64(o) ((o) ^ (((o) >> 3) & 0x30))

#define CP16(dst, src)                                                         \
    asm volatile("cp.async.cg.shared.global [%0], [%1], 16;" ::                \
                 "r"(dst), "l"(src))

#define LDSM4(r0, r1, r2, r3, a)                                               \
    asm volatile("ldmatrix.sync.aligned.m8n8.x4.shared.b16 {%0,%1,%2,%3},[%4];"\
                 : "=r"(r0), "=r"(r1), "=r"(r2), "=r"(r3) : "r"(a))

#define MMA_BF16(d, a, b)                                                      \
    asm volatile("mma.sync.aligned.m16n8k16.row.col.f32.bf16.bf16.f32 "        \
                 "{%0,%1,%2,%3},{%4,%5,%6,%7},{%8,%9},{%0,%1,%2,%3};"          \
                 : "+f"((d)[0]), "+f"((d)[1]), "+f"((d)[2]), "+f"((d)[3])      \
                 : "r"((a)[0]), "r"((a)[1]), "r"((a)[2]), "r"((a)[3]),         \
                   "r"((b)[0]), "r"((b)[1]))

// ---------------------------------------------------------------------------
// Split-bf16 3-term GEMM: C[M,N] = (Ah+Al)[M,K] @ ((Bh+Bl)[N,K])^T
// CTA 128x128, 256 threads (8 warps of 64x32), BK=32, 3-stage cp.async,
// SW64-swizzled 64B rows, ONE __syncthreads per k-chunk.
// ---------------------------------------------------------------------------
#define BKE   32
#define TILEB 8192
#define OFF_AH 0
#define OFF_AL (1*TILEB)
#define OFF_BH (2*TILEB)
#define OFF_BL (3*TILEB)
#define STG    (4*TILEB)            // 32768 bytes per stage
#define NSTG   3
#define GEMM_SMEM (NSTG*STG)        // 98304

__device__ __forceinline__ void load_stage(
    const __nv_bfloat16* __restrict__ Ah, const __nv_bfloat16* __restrict__ Al,
    const __nv_bfloat16* __restrict__ Bh, const __nv_bfloat16* __restrict__ Bl,
    int bm, int bn, int K, int kc, uint32_t sbase, int tid)
{
#pragma unroll
    for (int i = 0; i < 2; i++) {
        int c    = tid + 256 * i;
        int row  = c >> 2;
        int k16  = c & 3;
        uint32_t off = SWZ64((uint32_t)(row * 64 + k16 * 16));
        size_t gofs = (size_t)kc * BKE + k16 * 8;
        CP16(sbase + OFF_AH + off, Ah + (size_t)(bm + row) * K + gofs);
        CP16(sbase + OFF_AL + off, Al + (size_t)(bm + row) * K + gofs);
        CP16(sbase + OFF_BH + off, Bh + (size_t)(bn + row) * K + gofs);
        CP16(sbase + OFF_BL + off, Bl + (size_t)(bn + row) * K + gofs);
    }
    asm volatile("cp.async.commit_group;" ::: "memory");
}

__global__ __launch_bounds__(256) void gemm_bf16_3t(
    const __nv_bfloat16* __restrict__ Ah, const __nv_bfloat16* __restrict__ Al,
    const __nv_bfloat16* __restrict__ Bh, const __nv_bfloat16* __restrict__ Bl,
    float* __restrict__ C, int M, int N, int K)
{
    extern __shared__ __align__(128) char smem[];
    const uint32_t sb = (uint32_t)__cvta_generic_to_shared(smem);
    const int tid  = threadIdx.x;
    const int lane = tid & 31;
    const int wid  = tid >> 5;
    const int wm   = (wid >> 2) * 64;
    const int wn   = (wid & 3) * 32;
    const int bm = blockIdx.y * 128;
    const int bn = blockIdx.x * 128;

    float acc[4][4][4];
#pragma unroll
    for (int mf = 0; mf < 4; mf++)
#pragma unroll
        for (int nf = 0; nf < 4; nf++)
#pragma unroll
            for (int i = 0; i < 4; i++) acc[mf][nf][i] = 0.f;

    const int NC = K / BKE;
    load_stage(Ah, Al, Bh, Bl, bm, bn, K, 0, sb + 0 * STG, tid);
    load_stage(Ah, Al, Bh, Bl, bm, bn, K, 1, sb + 1 * STG, tid);

    const int lrow = lane & 15;
    const int lkb  = (lane >> 4) * 16;

    int buf = 0, nxt = 2;
    for (int c = 0; c < NC; c++) {
        if (c + 1 < NC) asm volatile("cp.async.wait_group 1;" ::: "memory");
        else            asm volatile("cp.async.wait_group 0;" ::: "memory");
        __syncthreads();

        if (c + 2 < NC)
            load_stage(Ah, Al, Bh, Bl, bm, bn, K, c + 2, sb + nxt * STG, tid);

        const uint32_t base = sb + buf * STG;
#pragma unroll
        for (int ks = 0; ks < 2; ks++) {
            const int kb = ks * 32 + lkb;
            uint32_t ah[4][4], al[4][4], bh[4][2], bl[4][2];
#pragma unroll
            for (int mf = 0; mf < 4; mf++) {
                uint32_t off = SWZ64((uint32_t)((wm + mf * 16 + lrow) * 64 + kb));
                LDSM4(ah[mf][0], ah[mf][1], ah[mf][2], ah[mf][3], base + OFF_AH + off);
                LDSM4(al[mf][0], al[mf][1], al[mf][2], al[mf][3], base + OFF_AL + off);
            }
#pragma unroll
            for (int nf2 = 0; nf2 < 2; nf2++) {
                uint32_t off = SWZ64((uint32_t)((wn + nf2 * 16 + lrow) * 64 + kb));
                uint32_t t0, t1, t2, t3;
                LDSM4(t0, t1, t2, t3, base + OFF_BH + off);
                bh[nf2 * 2 + 0][0] = t0; bh[nf2 * 2 + 0][1] = t2;
                bh[nf2 * 2 + 1][0] = t1; bh[nf2 * 2 + 1][1] = t3;
                LDSM4(t0, t1, t2, t3, base + OFF_BL + off);
                bl[nf2 * 2 + 0][0] = t0; bl[nf2 * 2 + 0][1] = t2;
                bl[nf2 * 2 + 1][0] = t1; bl[nf2 * 2 + 1][1] = t3;
            }
#pragma unroll
            for (int mf = 0; mf < 4; mf++)
#pragma unroll
                for (int nf = 0; nf < 4; nf++) {
                    MMA_BF16(acc[mf][nf], ah[mf], bh[nf]);
                    MMA_BF16(acc[mf][nf], ah[mf], bl[nf]);
                    MMA_BF16(acc[mf][nf], al[mf], bh[nf]);
                }
        }

        buf = (buf + 1 == NSTG) ? 0 : buf + 1;
        nxt = (nxt + 1 == NSTG) ? 0 : nxt + 1;
    }

    const int g   = lane >> 2;
    const int tig = lane & 3;
#pragma unroll
    for (int mf = 0; mf < 4; mf++)
#pragma unroll
        for (int nf = 0; nf < 4; nf++) {
            int r  = bm + wm + mf * 16 + g;
            int cc = bn + wn + nf * 8 + tig * 2;
            *reinterpret_cast<float2*>(&C[(size_t)r * N + cc]) =
                make_float2(acc[mf][nf][0], acc[mf][nf][1]);
            *reinterpret_cast<float2*>(&C[(size_t)(r + 8) * N + cc]) =
                make_float2(acc[mf][nf][2], acc[mf][nf][3]);
        }
}

// ---------------------------------------------------------------------------
// split fp32 -> bf16 hi/lo
// ---------------------------------------------------------------------------
__global__ __launch_bounds__(256) void split_bf16(
    const float4* __restrict__ in, __nv_bfloat16* __restrict__ h,
    __nv_bfloat16* __restrict__ l, int n4)
{
    int i = blockIdx.x * 256 + threadIdx.x;
    if (i >= n4) return;
    float4 v = in[i];
    __nv_bfloat16 h0, l0, h1, l1, h2, l2, h3, l3;
    bsplit(v.x, h0, l0); bsplit(v.y, h1, l1);
    bsplit(v.z, h2, l2); bsplit(v.w, h3, l3);
    __nv_bfloat162* hp = (__nv_bfloat162*)(h + (size_t)i * 4);
    __nv_bfloat162* lp = (__nv_bfloat162*)(l + (size_t)i * 4);
    hp[0] = __nv_bfloat162(h0, h1); hp[1] = __nv_bfloat162(h2, h3);
    lp[0] = __nv_bfloat162(l0, l1); lp[1] = __nv_bfloat162(l2, l3);
}

// ---------------------------------------------------------------------------
// transpose + split: W[K][N] fp32 -> Th/Tl[N][K] bf16
// ---------------------------------------------------------------------------
__global__ __launch_bounds__(256) void split_bf16_T(
    const float* __restrict__ W, __nv_bfloat16* __restrict__ Th,
    __nv_bfloat16* __restrict__ Tl, int K, int N)
{
    __shared__ float tile[32][33];
    const int bx = blockIdx.x * 32;   // N
    const int by = blockIdx.y * 32;   // K
    const int tx = threadIdx.x & 31, ty = threadIdx.x >> 5;
#pragma unroll
    for (int i = 0; i < 32; i += 8)
        tile[ty + i][tx] = W[(size_t)(by + ty + i) * N + bx + tx];
    __syncthreads();
#pragma unroll
    for (int i = 0; i < 32; i += 8) {
        float v = tile[tx][ty + i];
        __nv_bfloat16 h, l;
        bsplit(v, h, l);
        size_t o = (size_t)(bx + ty + i) * K + by + tx;
        Th[o] = h; Tl[o] = l;
    }
}

// ---------------------------------------------------------------------------
// Causal depthwise conv (KW=4) + SiLU
// ---------------------------------------------------------------------------
__global__ __launch_bounds__(256) void conv_silu(
    const float* __restrict__ pre, const float* __restrict__ cw,
    const float* __restrict__ cb, float* __restrict__ out)
{
    int c = blockIdx.x * 256 + threadIdx.x;
    int t = blockIdx.y;
    int b = t / SS, s = t % SS;
    float acc = cb[c];
#pragma unroll
    for (int j = 0; j < KW; j++) {
        int sp = s - (KW - 1) + j;
        if (sp >= 0)
            acc += pre[(size_t)(b * SS + sp) * CONV_DIM + c] * cw[c * KW + j];
    }
    out[(size_t)t * CONV_DIM + c] = acc / (1.f + expf(-acc));
}

// ---------------------------------------------------------------------------
// beta / g projections
// ---------------------------------------------------------------------------
__global__ __launch_bounds__(256) void proj_gb(
    const float* __restrict__ x, const float* __restrict__ Wb,
    const float* __restrict__ Wa, const float* __restrict__ dt_bias,
    const float* __restrict__ A_log, float* __restrict__ gout,
    float* __restrict__ bout)
{
    int t = blockIdx.x;
    __shared__ float xs[HH];
    const float4* xr = reinterpret_cast<const float4*>(x + (size_t)t * HH);
    float4* xs4 = reinterpret_cast<float4*>(xs);
    for (int i = threadIdx.x; i < HH / 4; i += 256) xs4[i] = xr[i];
    __syncthreads();

    int out  = threadIdx.x >> 2;
    int part = threadIdx.x & 3;
    const float* W = (out < 32) ? Wb : Wa;
    int col = out & 31;

    float acc = 0.f;
    int k0 = part * (HH / 4);
#pragma unroll 8
    for (int k = k0; k < k0 + HH / 4; k++)
        acc += xs[k] * W[k * HV + col];

    acc += __shfl_xor_sync(0xffffffffu, acc, 1);
    acc += __shfl_xor_sync(0xffffffffu, acc, 2);

    if (part == 0) {
        if (out < 32) {
            bout[t * HV + col] = 1.f / (1.f + expf(-acc));
        } else {
            float v = acc + dt_bias[col];
            float sp = (v > 20.f) ? v : log1pf(expf(v));
            gout[t * HV + col] = -expf(A_log[col]) * sp;
        }
    }
}

// ---------------------------------------------------------------------------
// q/k l2-normalization + head-repeat
// ---------------------------------------------------------------------------
__global__ __launch_bounds__(128) void qk_prep(
    const float* __restrict__ mixed, float* __restrict__ qn,
    float* __restrict__ kn)
{
    int blk = blockIdx.x;
    int t = blk / HK, hk = blk % HK;
    int dk = threadIdx.x;

    float qv = mixed[(size_t)t * CONV_DIM + hk * DK + dk];
    float kv = mixed[(size_t)t * CONV_DIM + KEY_DIM + hk * DK + dk];

    __shared__ float s1[128], s2[128];
    s1[dk] = qv * qv;
    s2[dk] = kv * kv;
    __syncthreads();
#pragma unroll
    for (int off = 64; off > 0; off >>= 1) {
        if (dk < off) { s1[dk] += s1[dk + off]; s2[dk] += s2[dk + off]; }
        __syncthreads();
    }
    __shared__ float rq, rk;
    if (dk == 0) {
        rq = rsqrtf(s1[0] + 1e-6f);
        rk = rsqrtf(s2[0] + 1e-6f);
    }
    __syncthreads();

    float qo = qv * rq * 0.08838834764831845f;
    float ko = kv * rk;
    int h0 = hk * 2;
    size_t base0 = ((size_t)t * HV + h0) * DK + dk;
    size_t base1 = ((size_t)t * HV + h0 + 1) * DK + dk;
    qn[base0] = qo; qn[base1] = qo;
    kn[base0] = ko; kn[base1] = ko;
}

// ---------------------------------------------------------------------------
// Gated delta-rule recurrence, 128 CTAs (2 per chain, dv-halved), smem-reduce.
// Time-chunked: [s_begin, s_end) with exact fp32 state carry via g_state.
// ---------------------------------------------------------------------------
__global__ __launch_bounds__(128) void recurrence(
    const float* __restrict__ qn, const float* __restrict__ kn,
    const float* __restrict__ mixed, const float* __restrict__ gg,
    const float* __restrict__ bb, float* __restrict__ core,
    float* __restrict__ state, int s_begin, int s_end,
    int load_st, int store_st)
{
    const int cid   = blockIdx.x;          // 0..127
    const int chain = cid >> 1;            // b*HV + h
    const int dvh   = (cid & 1) * 64;
    const int b = chain / HV, h = chain % HV;
    const int tid = threadIdx.x;
    const int dvl = tid & 63;
    const int dkh = (tid >> 6) * 64;
    const int dv  = dvh + dvl;
    const size_t stbase = (size_t)chain * (DK * DV);

    float st[64];
    if (load_st) {
#pragma unroll
        for (int i = 0; i < 64; i++)
            st[i] = state[stbase + (size_t)(dkh + i) * DV + dv];
    } else {
#pragma unroll
        for (int i = 0; i < 64; i++) st[i] = 0.f;
    }

    __shared__ float ks[2][DK], qs[2][DK], red1[128], red2[128];

    const int t0 = b * SS + s_begin;
    ks[s_begin & 1][tid] = kn[((size_t)t0 * HV + h) * DK + tid];
    qs[s_begin & 1][tid] = qn[((size_t)t0 * HV + h) * DK + tid];
    float gv = gg[t0 * HV + h];
    float bv = bb[t0 * HV + h];
    float vv = mixed[(size_t)t0 * CONV_DIM + 2 * KEY_DIM + h * DV + dv];
    __syncthreads();

    for (int s = s_begin; s < s_end; s++) {
        const int cur = s & 1;
        const int t = b * SS + s;

        float knx = 0.f, qnx = 0.f, gnx = 0.f, bnx = 0.f, vnx = 0.f;
        if (s + 1 < s_end) {
            int tn = t + 1;
            knx = kn[((size_t)tn * HV + h) * DK + tid];
            qnx = qn[((size_t)tn * HV + h) * DK + tid];
            gnx = gg[tn * HV + h];
            bnx = bb[tn * HV + h];
            vnx = mixed[(size_t)tn * CONV_DIM + 2 * KEY_DIM + h * DV + dv];
        }

        const float dec = expf(gv);

        float m0 = 0.f, m1 = 0.f, m2 = 0.f, m3 = 0.f;
#pragma unroll
        for (int i = 0; i < 64; i += 4) {
            float4 kk = *reinterpret_cast<const float4*>(&ks[cur][dkh + i]);
            st[i + 0] *= dec; m0 += kk.x * st[i + 0];
            st[i + 1] *= dec; m1 += kk.y * st[i + 1];
            st[i + 2] *= dec; m2 += kk.z * st[i + 2];
            st[i + 3] *= dec; m3 += kk.w * st[i + 3];
        }
        red1[tid] = (m0 + m1) + (m2 + m3);
        __syncthreads();
        const float mem = red1[tid] + red1[tid ^ 64];
        const float delta = (vv - mem) * bv;

        float o0 = 0.f, o1 = 0.f, o2 = 0.f, o3 = 0.f;
#pragma unroll
        for (int i = 0; i < 64; i += 4) {
            float4 kk = *reinterpret_cast<const float4*>(&ks[cur][dkh + i]);
            float4 qq = *reinterpret_cast<const float4*>(&qs[cur][dkh + i]);
            st[i + 0] += kk.x * delta; o0 += qq.x * st[i + 0];
            st[i + 1] += kk.y * delta; o1 += qq.y * st[i + 1];
            st[i + 2] += kk.z * delta; o2 += qq.z * st[i + 2];
            st[i + 3] += kk.w * delta; o3 += qq.w * st[i + 3];
        }
        red2[tid] = (o0 + o1) + (o2 + o3);

        if (s + 1 < s_end) {
            ks[cur ^ 1][tid] = knx;
            qs[cur ^ 1][tid] = qnx;
        }
        __syncthreads();
        if (dkh == 0)
            core[((size_t)t * HV + h) * DV + dv] = red2[tid] + red2[tid ^ 64];

        gv = gnx; bv = bnx; vv = vnx;
    }

    if (store_st) {
#pragma unroll
        for (int i = 0; i < 64; i++)
            state[stbase + (size_t)(dkh + i) * DV + dv] = st[i];
    }
}

// ---------------------------------------------------------------------------
// gated RMSNorm -> bf16 hi/lo; t_off selects the token slice
// ---------------------------------------------------------------------------
__global__ __launch_bounds__(128) void gated_norm(
    const float* __restrict__ core, const float* __restrict__ z,
    const float* __restrict__ nw, __nv_bfloat16* __restrict__ nh,
    __nv_bfloat16* __restrict__ nl, int t_off)
{
    int bh = blockIdx.x + t_off * HV;
    int dv = threadIdx.x;
    size_t idx = (size_t)bh * DV + dv;

    float c  = core[idx];
    float zv = z[idx];
    float gz = c * (zv / (1.f + expf(-zv)));

    __shared__ float red[128];
    red[dv] = gz * gz;
    __syncthreads();
#pragma unroll
    for (int off = 64; off > 0; off >>= 1) {
        if (dv < off) red[dv] += red[dv + off];
        __syncthreads();
    }
    __shared__ float rs;
    if (dv == 0) rs = rsqrtf(red[0] * (1.f / DV) + 1e-6f);
    __syncthreads();

    __nv_bfloat16 h, l;
    bsplit(gz * rs * nw[dv], h, l);
    nh[idx] = h; nl[idx] = l;
}

// ---------------------------------------------------------------------------
// launch — 3-stream pipelined overlap (graph-capturable event fork/join)
// ---------------------------------------------------------------------------
extern "C" void kernel_launch(void* const* d_in, const int* in_sizes, int n_in,
                              void* d_out, int out_size)
{
    const float* x       = (const float*)d_in[0];
    const float* Wqkv    = (const float*)d_in[1];
    const float* Wz      = (const float*)d_in[2];
    const float* Wb      = (const float*)d_in[3];
    const float* Wa      = (const float*)d_in[4];
    const float* conv_w  = (const float*)d_in[5];
    const float* conv_b  = (const float*)d_in[6];
    const float* dt_bias = (const float*)d_in[7];
    const float* A_log   = (const float*)d_in[8];
    const float* norm_w  = (const float*)d_in[9];
    const float* Wout    = (const float*)d_in[10];
    float* out = (float*)d_out;

    float *qkv_pre, *mixed, *z, *qn, *kn, *gbuf, *bbuf, *core, *state;
    __nv_bfloat16 *xh, *xl, *WqT_h, *WqT_l, *WzT_h, *WzT_l, *WoT_h, *WoT_l, *nh, *nl;
    cudaGetSymbolAddress((void**)&qkv_pre, g_qkv_pre);
    cudaGetSymbolAddress((void**)&mixed,   g_mixed);
    cudaGetSymbolAddress((void**)&z,       g_z);
    cudaGetSymbolAddress((void**)&qn,      g_qn);
    cudaGetSymbolAddress((void**)&kn,      g_kn);
    cudaGetSymbolAddress((void**)&gbuf,    g_g);
    cudaGetSymbolAddress((void**)&bbuf,    g_beta);
    cudaGetSymbolAddress((void**)&core,    g_core);
    cudaGetSymbolAddress((void**)&state,   g_state);
    cudaGetSymbolAddress((void**)&xh,      g_xh);
    cudaGetSymbolAddress((void**)&xl,      g_xl);
    cudaGetSymbolAddress((void**)&WqT_h,   g_WqkvT_h);
    cudaGetSymbolAddress((void**)&WqT_l,   g_WqkvT_l);
    cudaGetSymbolAddress((void**)&WzT_h,   g_WzT_h);
    cudaGetSymbolAddress((void**)&WzT_l,   g_WzT_l);
    cudaGetSymbolAddress((void**)&WoT_h,   g_WoutT_h);
    cudaGetSymbolAddress((void**)&WoT_l,   g_WoutT_l);
    cudaGetSymbolAddress((void**)&nh,      g_nrm_h);
    cudaGetSymbolAddress((void**)&nl,      g_nrm_l);

    static cudaStream_t s1 = nullptr, s2 = nullptr;
    static cudaEvent_t ev_root, ev_prep, ev_qkv, ev_z0, ev_z1, ev_rec0, ev_out1;
    if (!s1) {
        cudaStreamCreateWithFlags(&s1, cudaStreamNonBlocking);
        cudaStreamCreateWithFlags(&s2, cudaStreamNonBlocking);
        cudaEventCreateWithFlags(&ev_root, cudaEventDisableTiming);
        cudaEventCreateWithFlags(&ev_prep, cudaEventDisableTiming);
        cudaEventCreateWithFlags(&ev_qkv,  cudaEventDisableTiming);
        cudaEventCreateWithFlags(&ev_z0,   cudaEventDisableTiming);
        cudaEventCreateWithFlags(&ev_z1,   cudaEventDisableTiming);
        cudaEventCreateWithFlags(&ev_rec0, cudaEventDisableTiming);
        cudaEventCreateWithFlags(&ev_out1, cudaEventDisableTiming);
        cudaFuncSetAttribute(gemm_bf16_3t,
            cudaFuncAttributeMaxDynamicSharedMemorySize, GEMM_SMEM);
    }

    // fork s1 off main
    cudaEventRecord(ev_root, 0);
    cudaStreamWaitEvent(s1, ev_root, 0);

    // main: x split + Wqkv split -> qkv GEMM
    split_bf16<<<(TT * HH / 4 + 255) / 256, 256>>>(
        (const float4*)x, xh, xl, TT * HH / 4);
    split_bf16_T<<<dim3(CONV_DIM / 32, HH / 32), 256>>>(
        Wqkv, WqT_h, WqT_l, HH, CONV_DIM);

    // s1: Wz/Wout splits + proj_gb (overlap qkv GEMM)
    split_bf16_T<<<dim3(VAL_DIM / 32, HH / 32), 256, 0, s1>>>(
        Wz, WzT_h, WzT_l, HH, VAL_DIM);
    split_bf16_T<<<dim3(HH / 32, VAL_DIM / 32), 256, 0, s1>>>(
        Wout, WoT_h, WoT_l, VAL_DIM, HH);
    proj_gb<<<TT, 256, 0, s1>>>(x, Wb, Wa, dt_bias, A_log, gbuf, bbuf);
    cudaEventRecord(ev_prep, s1);

    // main: qkv GEMM
    gemm_bf16_3t<<<dim3(CONV_DIM / 128, TT / 128), 256, GEMM_SMEM>>>(
        xh, xl, WqT_h, WqT_l, qkv_pre, TT, CONV_DIM, HH);
    cudaEventRecord(ev_qkv, 0);

    // s1: z GEMM chunked by token rows: chunk0 = tokens [0,512)+[1024,1536)
    cudaStreamWaitEvent(s1, ev_qkv, 0);
    gemm_bf16_3t<<<dim3(VAL_DIM / 128, SHALF / 128), 256, GEMM_SMEM, s1>>>(
        xh, xl, WzT_h, WzT_l, z, SHALF, VAL_DIM, HH);
    gemm_bf16_3t<<<dim3(VAL_DIM / 128, SHALF / 128), 256, GEMM_SMEM, s1>>>(
        xh + (size_t)SS * HH, xl + (size_t)SS * HH, WzT_h, WzT_l,
        z + (size_t)SS * VAL_DIM, SHALF, VAL_DIM, HH);
    cudaEventRecord(ev_z0, s1);
    gemm_bf16_3t<<<dim3(VAL_DIM / 128, SHALF / 128), 256, GEMM_SMEM, s1>>>(
        xh + (size_t)SHALF * HH, xl + (size_t)SHALF * HH, WzT_h, WzT_l,
        z + (size_t)SHALF * VAL_DIM, SHALF, VAL_DIM, HH);
    gemm_bf16_3t<<<dim3(VAL_DIM / 128, SHALF / 128), 256, GEMM_SMEM, s1>>>(
        xh + (size_t)(SS + SHALF) * HH, xl + (size_t)(SS + SHALF) * HH,
        WzT_h, WzT_l, z + (size_t)(SS + SHALF) * VAL_DIM, SHALF, VAL_DIM, HH);
    cudaEventRecord(ev_z1, s1);

    // main: conv + qk prep + rec chunk 0 (s in [0,512))
    conv_silu<<<dim3(CONV_DIM / 256, TT), 256>>>(qkv_pre, conv_w, conv_b, mixed);
    qk_prep<<<TT * HK, 128>>>(mixed, qn, kn);
    cudaStreamWaitEvent(0, ev_prep, 0);
    recurrence<<<BB * HV * 2, 128>>>(qn, kn, mixed, gbuf, bbuf, core,
                                     state, 0, SHALF, 0, 1);
    cudaEventRecord(ev_rec0, 0);

    // s2: norm + out-GEMM for chunk-0 token slices (overlaps rec chunk 1)
    cudaStreamWaitEvent(s2, ev_z0, 0);
    cudaStreamWaitEvent(s2, ev_rec0, 0);
    gated_norm<<<SHALF * HV, 128, 0, s2>>>(core, z, norm_w, nh, nl, 0);
    gated_norm<<<SHALF * HV, 128, 0, s2>>>(core, z, norm_w, nh, nl, SS);
    gemm_bf16_3t<<<dim3(HH / 128, SHALF / 128), 256, GEMM_SMEM, s2>>>(
        nh, nl, WoT_h, WoT_l, out, SHALF, HH, VAL_DIM);
    gemm_bf16_3t<<<dim3(HH / 128, SHALF / 128), 256, GEMM_SMEM, s2>>>(
        nh + (size_t)SS * VAL_DIM, nl + (size_t)SS * VAL_DIM, WoT_h, WoT_l,
        out + (size_t)SS * HH, SHALF, HH, VAL_DIM);
    cudaEventRecord(ev_out1, s2);

    // main: rec chunk 1 (s in [512,1024)), then norm+out for chunk-1 slices
    recurrence<<<BB * HV * 2, 128>>>(qn, kn, mixed, gbuf, bbuf, core,
                                     state, SHALF, SS, 1, 0);
    cudaStreamWaitEvent(0, ev_z1, 0);
    gated_norm<<<SHALF * HV, 128>>>(core, z, norm_w, nh, nl, SHALF);
    gated_norm<<<SHALF * HV, 128>>>(core, z, norm_w, nh, nl, SS + SHALF);
    gemm_bf16_3t<<<dim3(HH / 128, SHALF / 128), 256, GEMM_SMEM>>>(
        nh + (size_t)SHALF * VAL_DIM, nl + (size_t)SHALF * VAL_DIM,
        WoT_h, WoT_l, out + (size_t)SHALF * HH, SHALF, HH, VAL_DIM);
    gemm_bf16_3t<<<dim3(HH / 128, SHALF / 128), 256, GEMM_SMEM>>>(
        nh + (size_t)(SS + SHALF) * VAL_DIM, nl + (size_t)(SS + SHALF) * VAL_DIM,
        WoT_h, WoT_l, out + (size_t)(SS + SHALF) * HH, SHALF, HH, VAL_DIM);

    // join s2 back into main before capture ends
    cudaStreamWaitEvent(0, ev_out1, 0);
}